// round 16
// baseline (speedup 1.0000x reference)
#include <cuda_runtime.h>
#include <cuda_fp16.h>
#include <math.h>
#include <stdint.h>

// ===========================================================================
// MotionCompensationBlock — HMMA fp16, implicit-tap GEMM
// Round 16: K-chunk 64 (per-slot tap) for M128 GEMMs; halved syncs/staging
// ===========================================================================

__device__ __forceinline__ uint32_t smem_u32(const void* p) {
    uint32_t a;
    asm("{ .reg .u64 t; cvta.to.shared.u64 t, %1; cvt.u32.u64 %0, t; }" : "=r"(a) : "l"(p));
    return a;
}

#define CP16(dst, src) \
    asm volatile("cp.async.cg.shared.global [%0], [%1], 16;" :: "r"(dst), "l"(src) : "memory")
#define CP_COMMIT() asm volatile("cp.async.commit_group;" ::: "memory")
#define CP_WAIT(n)  asm volatile("cp.async.wait_group %0;" :: "n"(n) : "memory")
#define ZSTS16(addr) \
    asm volatile("st.shared.v4.b32 [%0], {%1,%1,%1,%1};" :: "r"(addr), "r"(0u) : "memory")

#define LDSM4(r, addr) \
    asm volatile("ldmatrix.sync.aligned.m8n8.x4.shared.b16 {%0,%1,%2,%3}, [%4];" \
                 : "=r"((r)[0]), "=r"((r)[1]), "=r"((r)[2]), "=r"((r)[3]) : "r"(addr))

__device__ __forceinline__ void mma16816(float* c, const uint32_t* a,
                                         uint32_t b0, uint32_t b1) {
    asm volatile(
        "mma.sync.aligned.m16n8k16.row.col.f32.f16.f16.f32 "
        "{%0,%1,%2,%3}, {%4,%5,%6,%7}, {%8,%9}, {%0,%1,%2,%3};"
        : "+f"(c[0]), "+f"(c[1]), "+f"(c[2]), "+f"(c[3])
        : "r"(a[0]), "r"(a[1]), "r"(a[2]), "r"(a[3]), "r"(b0), "r"(b1));
}

__device__ __forceinline__ uint32_t pack_h2(float v0, float v1) {
    __half2 hp = __halves2half2(__float2half(v0), __float2half(v1));
    return *(uint32_t*)&hp;
}

// ------------------------------ pools --------------------------------------
#define POOL_U32 (68u << 20)
__device__ uint32_t g_XH[POOL_U32];
#define O_XT0A  (0L)
#define O_XT0B  (6L  << 20)
#define O_SAMP0 (9L  << 20)
#define O_XT1A  (28L << 20)
#define O_XT1B  (31L << 20)
#define O_SAMP1 (33L << 20)
#define O_XT2A  (43L << 20)
#define O_XT2B  (45L << 20)
#define O_SAMP2 (46L << 20)
#define O_XTU1  (51L << 20)
#define O_XTF1  (54L << 20)
#define O_XTU0  (57L << 20)
#define O_XTF0  (62L << 20)

#define ASLOT 1253376
__device__ __half g_Ah[14L * ASLOT];   // 13 used + 1 pad slot for tail reads
__device__ float g_om0[14155776], g_om1[3538944], g_om2[884736];

// ------------------------------ streams ------------------------------------
struct MCStreams {
    cudaStream_t s1, s2;
    cudaEvent_t eF, eL0, eL1;
    MCStreams() {
        cudaStreamCreateWithFlags(&s1, cudaStreamNonBlocking);
        cudaStreamCreateWithFlags(&s2, cudaStreamNonBlocking);
        cudaEventCreateWithFlags(&eF,  cudaEventDisableTiming);
        cudaEventCreateWithFlags(&eL0, cudaEventDisableTiming);
        cudaEventCreateWithFlags(&eL1, cudaEventDisableTiming);
    }
};
static MCStreams g_s;

// ---------------------------------------------------------------------------
// xpose: NCHW fp32 (dual-source concat) -> Xt[n][c] fp16 pairs
// ---------------------------------------------------------------------------
__global__ void __launch_bounds__(256)
xpose(const float* __restrict__ s1, int c1, long bs1,
      const float* __restrict__ s2, int c2, long bs2,
      int H, int W, int Cph, uint32_t* __restrict__ Xh)
{
    __shared__ uint32_t sh[32][65];
    __shared__ int sp_b[64], sp_p[64];

    const int tid = threadIdx.x;
    const int cc0 = blockIdx.x * 32;
    const long n0 = (long)blockIdx.y * 64;
    const int HW = H * W;

    if (tid < 64) {
        long n = n0 + tid;
        int b = (int)(n / HW);
        sp_b[tid] = b;
        sp_p[tid] = (int)(n - (long)b * HW);
    }
    __syncthreads();

    const int Cin = c1 + c2;
#pragma unroll
    for (int e = tid; e < 2048; e += 256) {
        const int p = e & 63, cc = e >> 6;
        const int c = (cc0 + cc) * 2;
        float v0 = 0.f, v1 = 0.f;
        const int b = sp_b[p];
        const int sp = sp_p[p];
        if (c < c1)          v0 = s1[(long)b * bs1 + (long)c * HW + sp];
        else if (c < Cin)    v0 = s2[(long)b * bs2 + (long)(c - c1) * HW + sp];
        const int cn = c + 1;
        if (cn < c1)         v1 = s1[(long)b * bs1 + (long)cn * HW + sp];
        else if (cn < Cin)   v1 = s2[(long)b * bs2 + (long)(cn - c1) * HW + sp];
        sh[cc][p] = pack_h2(v0, v1);
    }
    __syncthreads();

#pragma unroll
    for (int e = tid; e < 2048; e += 256) {
        const int kk = e & 31, p = e >> 5;
        if (cc0 + kk < Cph)
            Xh[(n0 + p) * Cph + cc0 + kk] = sh[kk][p];
    }
}

// ---------------------------------------------------------------------------
// up2_xt: fused bilinear 2x upsample + transpose to Xt[n][c] fp16
// ---------------------------------------------------------------------------
__global__ void __launch_bounds__(256)
up2_xt(const float* __restrict__ src, int C, int Hs, int Ws, int Cph,
       uint32_t* __restrict__ Xh)
{
    __shared__ uint32_t sh[32][65];
    __shared__ int sb[64], si0[64], si1[64], si2[64], si3[64];
    __shared__ float swy[64], swx[64];

    const int tid = threadIdx.x;
    const int cc0 = blockIdx.x * 32;
    const long n0 = (long)blockIdx.y * 64;
    const int W2 = 2 * Ws, H2 = 2 * Hs;
    const int HW2 = H2 * W2;
    const int HWs = Hs * Ws;

    if (tid < 64) {
        long n = n0 + tid;
        int b = (int)(n / HW2);
        int p2 = (int)(n - (long)b * HW2);
        int oy = p2 / W2, ox = p2 % W2;
        float sy = fmaxf(oy * 0.5f - 0.25f, 0.f);
        float sx = fmaxf(ox * 0.5f - 0.25f, 0.f);
        int y0 = (int)floorf(sy); float ty = sy - (float)y0;
        int y1 = min(y0 + 1, Hs - 1);
        int x0 = (int)floorf(sx); float tx = sx - (float)x0;
        int x1 = min(x0 + 1, Ws - 1);
        sb[tid] = b;
        si0[tid] = y0 * Ws + x0; si1[tid] = y0 * Ws + x1;
        si2[tid] = y1 * Ws + x0; si3[tid] = y1 * Ws + x1;
        swy[tid] = ty; swx[tid] = tx;
    }
    __syncthreads();

#pragma unroll
    for (int e = tid; e < 2048; e += 256) {
        const int p = e & 63, cc = e >> 6;
        const int c = (cc0 + cc) * 2;
        const float ty = swy[p], tx = swx[p];
        const int i0 = si0[p], i1 = si1[p], i2 = si2[p], i3 = si3[p];
        const float* pc = src + ((long)sb[p] * C + c) * HWs;
        float a0 = pc[i0] * (1.f - ty) + pc[i2] * ty;
        float a1 = pc[i1] * (1.f - ty) + pc[i3] * ty;
        float v0 = a0 * (1.f - tx) + a1 * tx;
        const float* pd = pc + HWs;
        float b0 = pd[i0] * (1.f - ty) + pd[i2] * ty;
        float b1 = pd[i1] * (1.f - ty) + pd[i3] * ty;
        float v1 = b0 * (1.f - tx) + b1 * tx;
        sh[cc][p] = pack_h2(v0, v1);
    }
    __syncthreads();

#pragma unroll
    for (int e = tid; e < 2048; e += 256) {
        const int kk = e & 31, p = e >> 5;
        Xh[(n0 + p) * Cph + cc0 + kk] = sh[kk][p];
    }
}

// ---------------------------------------------------------------------------
// Fused weight convert (fp16)
// ---------------------------------------------------------------------------
struct WJob {
    const float* w;
    uint32_t* Ah;
    int M, Cin, Cp, Kp, total;
};
struct WJobs { WJob j[13]; };

__global__ void __launch_bounds__(256)
wconv_all(WJobs jobs)
{
    const WJob jb = jobs.j[blockIdx.y];
    int idx = blockIdx.x * 256 + threadIdx.x;
    if (idx >= jb.total) return;
    const int Kh = jb.Kp >> 1;
    const int kk = idx % Kh;
    const int m  = idx / Kh;
    const int k0 = kk * 2;
    const int t = k0 / jb.Cp, c = k0 - t * jb.Cp;
    float v0 = 0.f, v1 = 0.f;
    if (m < jb.M && t < 9) {
        if (c < jb.Cin)     v0 = jb.w[((long)m * jb.Cin + c) * 9 + t];
        if (c + 1 < jb.Cin) v1 = jb.w[((long)m * jb.Cin + c + 1) * 9 + t];
    }
    jb.Ah[idx] = pack_h2(v0, v1);
}

// ===========================================================================
// GEMM geometry
//  M128 kernels: K-chunk 64, LROW 72, 3-stage (108KB, 2 CTAs/SM)
//  M64  kernels: K-chunk 32, LROW 40, 3-stage (75KB, 2 CTAs/SM)
// ===========================================================================
#define LROWW 72
#define PLW_B (128 * LROWW * 2)            // 18432 B per plane
#define STGW_B (2 * PLW_B)                 // 36864 B per stage
#define GEMM_SMEM (3 * STGW_B)             // 110592 B (>= epi 68096)

#define LROW 40
#define APL64_B (64 * LROW * 2)            // 5120 B
#define BPL64_B (256 * LROW * 2)           // 20480 B
#define STG64_B (APL64_B + BPL64_B)        // 25600 B
#define GEMM64_SMEM 76800                  // 3*STG64_B (>= epi 66816)

// M128 MMA body: 4 k16-steps per 64-chunk
#define MMA_BODYW(stgA, stgB)                                                  \
    _Pragma("unroll")                                                          \
    for (int s = 0; s < 4; s++) {                                              \
        const uint32_t cofs = (uint32_t)(s * 32);                              \
        uint32_t afh[4][4], bfh[2][4];                                         \
        _Pragma("unroll")                                                      \
        for (int mt = 0; mt < 4; mt++)                                         \
            LDSM4(afh[mt], (stgA) + aoff[mt] + cofs);                          \
        _Pragma("unroll")                                                      \
        for (int np = 0; np < 2; np++)                                         \
            LDSM4(bfh[np], (stgB) + boff[np] + cofs);                          \
        _Pragma("unroll")                                                      \
        for (int mt = 0; mt < 4; mt++)                                         \
            _Pragma("unroll")                                                  \
            for (int nt = 0; nt < 4; nt++) {                                   \
                const uint32_t* bh = &bfh[nt >> 1][(nt & 1) * 2];              \
                mma16816(acc[mt][nt], afh[mt], bh[0], bh[1]);                  \
            }                                                                  \
    }

// M64 MMA body: 2 k16-steps per 32-chunk
#define MMA_BODY1(stgA, stgB)                                                  \
    _Pragma("unroll")                                                          \
    for (int s = 0; s < 2; s++) {                                              \
        const uint32_t cofs = (uint32_t)(s * 32);                              \
        uint32_t afh[4][4], bfh[2][4];                                         \
        _Pragma("unroll")                                                      \
        for (int mt = 0; mt < 4; mt++)                                         \
            LDSM4(afh[mt], (stgA) + aoff[mt] + cofs);                          \
        _Pragma("unroll")                                                      \
        for (int np = 0; np < 2; np++)                                         \
            LDSM4(bfh[np], (stgB) + boff[np] + cofs);                          \
        _Pragma("unroll")                                                      \
        for (int mt = 0; mt < 4; mt++)                                         \
            _Pragma("unroll")                                                  \
            for (int nt = 0; nt < 4; nt++) {                                   \
                const uint32_t* bh = &bfh[nt >> 1][(nt & 1) * 2];              \
                mma16816(acc[mt][nt], afh[mt], bh[0], bh[1]);                  \
            }                                                                  \
    }

#define EPI_FP32_128()                                                         \
    {                                                                          \
        const int bIdx = p0 / HW, prow0 = p0 % HW;                             \
        _Pragma("unroll")                                                      \
        for (int mt = 0; mt < 4; mt++) {                                       \
            const int oca = m0 + wm * 64 + mt * 16 + g;                        \
            const int ocb = oca + 8;                                           \
            const float ba = (oca < Cout) ? bias[oca] : 0.f;                   \
            const float bb = (ocb < Cout) ? bias[ocb] : 0.f;                   \
            _Pragma("unroll")                                                  \
            for (int nt = 0; nt < 4; nt++) {                                   \
                const int pc = prow0 + wn * 32 + nt * 8 + 2 * t;               \
                if (oca < Cout) {                                              \
                    float2 v = make_float2(acc[mt][nt][0] + ba, acc[mt][nt][1] + ba); \
                    *(float2*)&out[((long)bIdx * ocStride + oca) * HW + pc] = v; \
                }                                                              \
                if (ocb < Cout) {                                              \
                    float2 v = make_float2(acc[mt][nt][2] + bb, acc[mt][nt][3] + bb); \
                    *(float2*)&out[((long)bIdx * ocStride + ocb) * HW + pc] = v; \
                }                                                              \
            }                                                                  \
        }                                                                      \
    }

#define EPI_XT_128()                                                           \
    {                                                                          \
        float* sf = (float*)sm;                                                \
        _Pragma("unroll")                                                      \
        for (int mt = 0; mt < 4; mt++) {                                       \
            const int ra = wm * 64 + mt * 16 + g;                              \
            const float ba = bias[m0 + ra];                                    \
            const float bb = bias[m0 + ra + 8];                                \
            _Pragma("unroll")                                                  \
            for (int nt = 0; nt < 4; nt++) {                                   \
                const int pc = wn * 32 + nt * 8 + 2 * t;                       \
                sf[ra * 133 + pc]           = acc[mt][nt][0] + ba;             \
                sf[ra * 133 + pc + 1]       = acc[mt][nt][1] + ba;             \
                sf[(ra + 8) * 133 + pc]     = acc[mt][nt][2] + bb;             \
                sf[(ra + 8) * 133 + pc + 1] = acc[mt][nt][3] + bb;             \
            }                                                                  \
        }                                                                      \
        __syncthreads();                                                       \
        const int cpBase = xtCpOff + (m0 >> 1);                                \
        for (int e = tid; e < 8192; e += 256) {                                \
            const int cp = e & 63, px = e >> 6;                                \
            xtH[(long)(p0 + px) * xtCph + cpBase + cp] =                       \
                pack_h2(sf[(2 * cp) * 133 + px], sf[(2 * cp + 1) * 133 + px]); \
        }                                                                      \
    }

#define EPI_FP32_64()                                                          \
    {                                                                          \
        const int bIdx = p0 / HW, prow0 = p0 % HW;                             \
        _Pragma("unroll")                                                      \
        for (int mt = 0; mt < 4; mt++) {                                       \
            const int oca = mt * 16 + g;                                       \
            const int ocb = oca + 8;                                           \
            const float ba = (oca < Cout) ? bias[oca] : 0.f;                   \
            const float bb = (ocb < Cout) ? bias[ocb] : 0.f;                   \
            _Pragma("unroll")                                                  \
            for (int nt = 0; nt < 4; nt++) {                                   \
                const int pc = prow0 + wn * 32 + nt * 8 + 2 * t;               \
                if (oca < Cout) {                                              \
                    float2 v = make_float2(acc[mt][nt][0] + ba, acc[mt][nt][1] + ba); \
                    *(float2*)&out[((long)bIdx * ocStride + oca) * HW + pc] = v; \
                }                                                              \
                if (ocb < Cout) {                                              \
                    float2 v = make_float2(acc[mt][nt][2] + bb, acc[mt][nt][3] + bb); \
                    *(float2*)&out[((long)bIdx * ocStride + ocb) * HW + pc] = v; \
                }                                                              \
            }                                                                  \
        }                                                                      \
    }

#define EPI_XT_64()                                                            \
    {                                                                          \
        float* sf = (float*)sm;                                                \
        _Pragma("unroll")                                                      \
        for (int mt = 0; mt < 4; mt++) {                                       \
            const int ra = mt * 16 + g;                                        \
            const float ba = bias[ra];                                         \
            const float bb = bias[ra + 8];                                     \
            _Pragma("unroll")                                                  \
            for (int nt = 0; nt < 4; nt++) {                                   \
                const int pc = wn * 32 + nt * 8 + 2 * t;                       \
                sf[ra * 261 + pc]           = acc[mt][nt][0] + ba;             \
                sf[ra * 261 + pc + 1]       = acc[mt][nt][1] + ba;             \
                sf[(ra + 8) * 261 + pc]     = acc[mt][nt][2] + bb;             \
                sf[(ra + 8) * 261 + pc + 1] = acc[mt][nt][3] + bb;             \
            }                                                                  \
        }                                                                      \
        __syncthreads();                                                       \
        for (int e = tid; e < 8192; e += 256) {                                \
            const int cp = e & 31, px = e >> 5;                                \
            xtH[(long)(p0 + px) * xtCph + xtCpOff + cp] =                      \
                pack_h2(sf[(2 * cp) * 261 + px], sf[(2 * cp + 1) * 261 + px]); \
        }                                                                      \
    }

// 3-stage loop skeleton (1 sync per chunk)
#define PIPE3_LOOP(STAGEFN, ADVANCE, MMAEXP)                                   \
    STAGEFN(0);                                                                \
    CP_COMMIT();                                                               \
    ADVANCE;                                                                   \
    if (nchunks > 1) { STAGEFN(1); }                                           \
    CP_COMMIT();                                                               \
    ADVANCE;                                                                   \
    for (int ci = 0; ci < nchunks; ci++) {                                     \
        CP_WAIT(1);                                                            \
        __syncthreads();                                                       \
        if (ci + 2 < nchunks) { STAGEFN((ci + 2) % 3); ADVANCE; }              \
        CP_COMMIT();                                                           \
        const uint32_t stg = smb + (uint32_t)(ci % 3) * stageBytes;            \
        MMAEXP                                                                 \
    }                                                                          \
    __syncthreads();

// ---------------------------------------------------------------------------
// gemm_tap: M128 x N128, implicit-tap B staging, K-chunk 64 (per-slot tap)
// ---------------------------------------------------------------------------
__global__ void __launch_bounds__(256, 2)
gemm_tap(const __half* __restrict__ Ahi,
         const uint32_t* __restrict__ Xh,
         const float* __restrict__ bias, float* __restrict__ out,
         int Kp, int Cp, int nchunks, int Cout, int ocStride, int H, int W,
         uint32_t* xtH, int xtCph, int xtCpOff)
{
    extern __shared__ __half sm[];
    const uint32_t stageBytes = STGW_B;

    const int tid = threadIdx.x, wid = tid >> 5, lane = tid & 31;
    const int g = lane >> 2, t = lane & 3;
    const int wm = wid >> 2, wn = wid & 3;
    const int HW = H * W;

    const int p0 = blockIdx.x * 128;
    const int m0 = blockIdx.y * 128;

    float acc[4][4][4];
#pragma unroll
    for (int i = 0; i < 4; i++)
#pragma unroll
        for (int j = 0; j < 4; j++)
#pragma unroll
            for (int k = 0; k < 4; k++) acc[i][j][k] = 0.f;

    const uint32_t smb = smem_u32(sm);
    const int rr = tid >> 1;          // staging row 0..127
    const int sb = (tid & 1) * 4;     // slot base (4 of 8 16B-slots)

    int brr, yrr, xrr;
    {
        int n = p0 + rr; brr = n / HW; int p = n - brr * HW; yrr = p / W; xrr = p - yrr * W;
    }

    uint32_t aoff[4], boff[2];
    {
        const int arow = (lane & 7) + ((lane >> 3) & 1) * 8;
        const int acol = (lane >> 4) * 8;
#pragma unroll
        for (int mt = 0; mt < 4; mt++)
            aoff[mt] = (uint32_t)(((wm * 64 + mt * 16 + arow) * LROWW + acol) * 2);
        const int brow = (lane & 7) + (lane >> 4) * 8;
        const int bcol = ((lane >> 3) & 1) * 8;
#pragma unroll
        for (int np = 0; np < 2; np++)
            boff[np] = (uint32_t)(((wn * 32 + np * 16 + brow) * LROWW + bcol) * 2);
    }

    const char* XhB = (const char*)Xh;
    const long rowB = (long)Cp * 2;

    int tP = 0, kinP = 0;
    auto stage = [&](int buf) {
        const uint32_t bufb = smb + (uint32_t)buf * STGW_B;
        const long kcA = (long)tP * Cp + kinP;
        const __half* aSrc = Ahi + (long)(m0 + rr) * Kp + kcA;
#pragma unroll
        for (int j = 0; j < 4; j++) {
            const int sl = sb + j;
            CP16(bufb + rr * 144 + sl * 16, aSrc + sl * 8);
        }
#pragma unroll
        for (int j = 0; j < 4; j++) {
            const int sl = sb + j;
            int koff = kinP + sl * 8;
            int tp = tP;
            if (koff >= Cp) { koff -= Cp; tp++; }
            const uint32_t dH = bufb + PLW_B + rr * 144 + sl * 16;
            bool ok = false;
            if (tp < 9) {
                const int q = tp / 3;
                const int yy = yrr + q - 1, xx = xrr + (tp - 3 * q - 1);
                if ((unsigned)yy < (unsigned)H && (unsigned)xx < (unsigned)W) {
                    CP16(dH, XhB + ((long)brr * HW + yy * W + xx) * rowB + (long)koff * 2);
                    ok = true;
                }
            }
            if (!ok) ZSTS16(dH);
        }
    };

#define ADV { kinP += 64; if (kinP >= Cp) { kinP -= Cp; tP++; } }
    PIPE3_LOOP(stage, ADV, MMA_BODYW(stg, stg + PLW_B))
#undef ADV

    if (xtH) EPI_XT_128()
    else     EPI_FP32_128()
}

// ---------------------------------------------------------------------------
// gemm_mma: M128 x N128 direct-B (DCN), K-chunk 64
// ---------------------------------------------------------------------------
__global__ void __launch_bounds__(256, 2)
gemm_mma(const __half* __restrict__ Ahi,
         const __half* __restrict__ Bhi,
         const float* __restrict__ bias, float* __restrict__ out,
         int Kp, int nchunks, int Cout, int ocStride, int HW,
         uint32_t* xtH, int xtCph, int xtCpOff)
{
    extern __shared__ __half sm[];
    const uint32_t stageBytes = STGW_B;

    const int tid = threadIdx.x, wid = tid >> 5, lane = tid & 31;
    const int g = lane >> 2, t = lane & 3;
    const int wm = wid >> 2, wn = wid & 3;

    const int p0 = blockIdx.x * 128;
    const int m0 = blockIdx.y * 128;

    float acc[4][4][4];
#pragma unroll
    for (int i = 0; i < 4; i++)
#pragma unroll
        for (int j = 0; j < 4; j++)
#pragma unroll
            for (int k = 0; k < 4; k++) acc[i][j][k] = 0.f;

    const uint32_t smb = smem_u32(sm);
    const int rr = tid >> 1;
    const int sb = (tid & 1) * 4;

    uint32_t aoff[4], boff[2];
    {
        const int arow = (lane & 7) + ((lane >> 3) & 1) * 8;
        const int acol = (lane >> 4) * 8;
#pragma unroll
        for (int mt = 0; mt < 4; mt++)
            aoff[mt] = (uint32_t)(((wm * 64 + mt * 16 + arow) * LROWW + acol) * 2);
        const int brow = (lane & 7) + (lane >> 4) * 8;
        const int bcol = ((lane >> 3) & 1) * 8;
#pragma unroll
        for (int np = 0; np < 2; np++)
            boff[np] = (uint32_t)(((wn * 32 + np * 16 + brow) * LROWW + bcol) * 2);
    }

    int ciP = 0;
    auto stage = [&](int buf) {
        const long kc = (long)ciP * 64;
        const uint32_t bufb = smb + (uint32_t)buf * STGW_B;
        const __half* aSrc = Ahi + (long)(m0 + rr) * Kp + kc;
        const __half* bSrc = Bhi + (long)(p0 + rr) * Kp + kc;
#pragma unroll
        for (int j = 0; j < 4; j++) {
            const int sl = sb + j;
            CP16(bufb + rr * 144 + sl * 16, aSrc + sl * 8);
            CP16(bufb + PLW_B + rr * 144 + sl * 16, bSrc + sl * 8);
        }
    };

#define ADV { ciP++; }
    PIPE3_LOOP(stage, ADV, MMA_BODYW(stg, stg + PLW_B))
#undef ADV

    if (xtH) EPI_XT_128()
    else     EPI_FP32_128()
}

// ---------------------------------------------------------------------------
// gemm_tap64: M64 x N256, implicit-tap, K-chunk 32 (unchanged geometry)
// ---------------------------------------------------------------------------
__global__ void __launch_bounds__(256, 2)
gemm_tap64(const __half* __restrict__ Ahi,
           const uint32_t* __restrict__ Xh,
           const float* __restrict__ bias, float* __restrict__ out,
           int Kp, int Cp, int nchunks, int Cout, int ocStride, int H, int W,
           uint32_t* xtH, int xtCph, int xtCpOff)
{
    extern __shared__ __half sm[];
    const uint32_t stageBytes = STG64_B;

    const int tid = threadIdx.x, wid = tid >> 5, lane = tid & 31;
    const int g = lane >> 2, t = lane & 3;
    const int wn = wid;
    const int HW = H * W;

    const int p0 = blockIdx.x * 256;

    float acc[4][4][4];
#pragma unroll
    for (int i = 0; i < 4; i++)
#pragma unroll
        for (int j = 0; j < 4; j++)
#pragma unroll
            for (int k = 0; k < 4; k++) acc[i][j][k] = 0.f;

    const uint32_t smb = smem_u32(sm);
    const int rA = tid >> 2, sA = tid & 3;

    int b4[4], y4[4], x4[4];
#pragma unroll
    for (int j = 0; j < 4; j++) {
        int n = p0 + rA + 64 * j;
        b4[j] = n / HW;
        int p = n - b4[j] * HW;
        y4[j] = p / W;
        x4[j] = p - y4[j] * W;
    }

    uint32_t aoff[4], boff[2];
    {
        const int arow = (lane & 7) + ((lane >> 3) & 1) * 8;
        const int acol = (lane >> 4) * 8;
#pragma unroll
        for (int mt = 0; mt < 4; mt++)
            aoff[mt] = (uint32_t)(((mt * 16 + arow) * LROW + acol) * 2);
        const int brow = (lane & 7) + (lane >> 4) * 8;
        const int bcol = ((lane >> 3) & 1) * 8;
#pragma unroll
        for (int np = 0; np < 2; np++)
            boff[np] = (uint32_t)(((wn * 32 + np * 16 + brow) * LROW + bcol) * 2);
    }

    const char* XhB = (const char*)Xh;
    const long rowB = (long)Cp * 2;

    int tP = 0, kinP = 0;
    auto stage = [&](int buf) {
        const long kc = (long)tP * Cp + kinP;
        const uint32_t bufb = smb + (uint32_t)buf * STG64_B;
        CP16(bufb + rA * 80 + sA * 16, Ahi + (long)rA * Kp + kc + sA * 8);
        const int q = tP / 3;
        const int dy = q - 1, dx = tP - 3 * q - 1;
        const long cb = (long)kinP * 2;
        const uint32_t bB = bufb + APL64_B;
#pragma unroll
        for (int j = 0; j < 4; j++) {
            const int r = rA + 64 * j;
            const int yy = y4[j] + dy, xx = x4[j] + dx;
            const uint32_t dH = bB + r * 80 + sA * 16;
            if ((unsigned)yy < (unsigned)H && (unsigned)xx < (unsigned)W)
                CP16(dH, XhB + ((long)b4[j] * HW + yy * W + xx) * rowB + cb + sA * 16);
            else ZSTS16(dH);
        }
    };

#define ADV { kinP += 32; if (kinP == Cp) { kinP = 0; tP++; } }
    PIPE3_LOOP(stage, ADV, MMA_BODY1(stg, stg + APL64_B))
#undef ADV

    if (xtH) EPI_XT_64()
    else     EPI_FP32_64()
}

// ---------------------------------------------------------------------------
// gemm_mma64: M64 x N256 direct-B (DCN), K-chunk 32 (unchanged)
// ---------------------------------------------------------------------------
__global__ void __launch_bounds__(256, 2)
gemm_mma64(const __half* __restrict__ Ahi,
           const __half* __restrict__ Bhi,
           const float* __restrict__ bias, float* __restrict__ out,
           int Kp, int nchunks, int Cout, int ocStride, int HW,
           uint32_t* xtH, int xtCph, int xtCpOff)
{
    extern __shared__ __half sm[];
    const uint32_t stageBytes = STG64_B;

    const int tid = threadIdx.x, wid = tid >> 5, lane = tid & 31;
    const int g = lane >> 2, t = lane & 3;
    const int wn = wid;

    const int p0 = blockIdx.x * 256;

    float acc[4][4][4];
#pragma unroll
    for (int i = 0; i < 4; i++)
#pragma unroll
        for (int j = 0; j < 4; j++)
#pragma unroll
            for (int k = 0; k < 4; k++) acc[i][j][k] = 0.f;

    const uint32_t smb = smem_u32(sm);
    const int rA = tid >> 2, sA = tid & 3;

    uint32_t aoff[4], boff[2];
    {
        const int arow = (lane & 7) + ((lane >> 3) & 1) * 8;
        const int acol = (lane >> 4) * 8;
#pragma unroll
        for (int mt = 0; mt < 4; mt++)
            aoff[mt] = (uint32_t)(((mt * 16 + arow) * LROW + acol) * 2);
        const int brow = (lane & 7) + (lane >> 4) * 8;
        const int bcol = ((lane >> 3) & 1) * 8;
#pragma unroll
        for (int np = 0; np < 2; np++)
            boff[np] = (uint32_t)(((wn * 32 + np * 16 + brow) * LROW + bcol) * 2);
    }

    int ciP = 0;
    auto stage = [&](int buf) {
        const long kc = (long)ciP * 32;
        const uint32_t bufb = smb + (uint32_t)buf * STG64_B;
        CP16(bufb + rA * 80 + sA * 16, Ahi + (long)rA * Kp + kc + sA * 8);
        const uint32_t bB = bufb + APL64_B;
#pragma unroll
        for (int j = 0; j < 4; j++) {
            const int task = tid + 256 * j;
            const int r = task >> 2, s = task & 3;
            CP16(bB + r * 80 + s * 16, Bhi + (long)(p0 + r) * Kp + kc + s * 8);
        }
    };

#define ADV { ciP++; }
    PIPE3_LOOP(stage, ADV, MMA_BODY1(stg, stg + APL64_B))
#undef ADV

    if (xtH) EPI_XT_64()
    else     EPI_FP32_64()
}

// ---------------------------------------------------------------------------
// DCN bilinear sampler (fp16)
// ---------------------------------------------------------------------------
__global__ void dcn_sample_bf(const float* __restrict__ x, long xbs,
                              const float* __restrict__ om,
                              uint4* __restrict__ Bh4,
                              int C, int H, int W, int total)
{
    int idx = blockIdx.x * blockDim.x + threadIdx.x;
    if (idx >= total) return;
    const int HW = H * W;
    const int p = idx % HW;
    const int k = (idx / HW) % 9;
    const int g = (idx / (HW * 9)) % 8;
    const int b = idx / (HW * 72);
    const int y = p / W, xq = p % W;

    const long omb = (long)b * 216 * HW + (long)(g * 9 + k) * HW + p;
    float dy = om[omb];
    float dx = om[omb + 72L * HW];
    float mk = om[omb + 144L * HW];
    mk = 1.f / (1.f + expf(-mk));

    float pyf = (float)y + (float)(k / 3 - 1) + dy;
    float pxf = (float)xq + (float)(k % 3 - 1) + dx;
    float y0f = floorf(pyf), x0f = floorf(pxf);
    int y0 = (int)y0f, x0i = (int)x0f;
    float ty = pyf - y0f, tx = pxf - x0f;
    int y1 = y0 + 1, x1i = x0i + 1;

    bool vy0 = (y0 >= 0) && (y0 < H), vy1 = (y1 >= 0) && (y1 < H);
    bool vx0 = (x0i >= 0) && (x0i < W), vx1 = (x1i >= 0) && (x1i < W);
    float w00 = (vy0 && vx0) ? (1.f - ty) * (1.f - tx) : 0.f;
    float w01 = (vy0 && vx1) ? (1.f - ty) * tx : 0.f;
    float w10 = (vy1 && vx0) ? ty * (1.f - tx) : 0.f;
    float w11 = (vy1 && vx1) ? ty * tx : 0.f;
    w00 *= mk; w01 *= mk; w10 *= mk; w11 *= mk;

    int cy0 = min(max(y0, 0), H - 1), cy1 = min(max(y1, 0), H - 1);
    int cx0 = min(max(x0i, 0), W - 1), cx1 = min(max(x1i, 0), W - 1);
    int i00 = cy0 * W + cx0, i01 = cy0 * W + cx1;
    int i10 = cy1 * W + cx0, i11 = cy1 * W + cx1;

    const int Cg = C >> 3;
    const int K = C * 9;
    const float* xb = x + (long)b * xbs + (long)g * Cg * HW;
    const long rowbase = ((long)b * HW + p) * K + (long)k * C + (long)g * Cg;
    const long o4 = rowbase >> 3;

    for (int cb = 0; cb < Cg; cb += 8) {
        uint32_t hv[4];
#pragma unroll
        for (int j = 0; j < 4; j++) {
            const float* xc0 = xb + (long)(cb + 2 * j) * HW;
            const float* xc1 = xc0 + HW;
            float v0 = w00 * xc0[i00] + w01 * xc0[i01] + w10 * xc0[i10] + w11 * xc0[i11];
            float v1 = w00 * xc1[i00] + w01 * xc1[i01] + w10 * xc1[i10] + w11 * xc1[i11];
            hv[j] = pack_h2(v0, v1);
        }
        Bh4[o4 + (cb >> 3)] = make_uint4(hv[0], hv[1], hv[2], hv[3]);
    }
}

// ---------------------------------------------------------------------------
extern "C" void kernel_launch(void* const* d_in, const int* in_sizes, int n_in,
                              void* d_out, int out_size)
{
    const float *x0 = nullptr, *x1 = nullptr, *x2 = nullptr;
    const float *flow0 = nullptr, *flow1 = nullptr, *flow2 = nullptr;
    for (int i = 0; i < 6; i++) {
        const float* p = (const float*)d_in[i];
        switch (in_sizes[i]) {
            case 4 * 2 * 64 * 128 * 128: x0 = p; break;
            case 4 * 2 * 128 * 64 * 64:  x1 = p; break;
            case 4 * 2 * 256 * 32 * 32:  x2 = p; break;
            case 4 * 2 * 128 * 128:      flow0 = p; break;
            case 4 * 2 * 64 * 64:        flow1 = p; break;
            case 4 * 2 * 32 * 32:        flow2 = p; break;
        }
    }
    const float* off_w0 = (const float*)d_in[6];  const float* off_b0 = (const float*)d_in[7];
    const float* co_w0  = (const float*)d_in[8];  const float* co_b0  = (const float*)d_in[9];
    const float* dcn_w0 = (const float*)d_in[10]; const float* dcn_b0 = (const float*)d_in[11];
    const float* off_w1 = (const float*)d_in[12]; const float* off_b1 = (const float*)d_in[13];
    const float* co_w1  = (const float*)d_in[14]; const float* co_b1  = (const float*)d_in[15];
    const float* dcn_w1 = (const float*)d_in[16]; const float* dcn_b1 = (const float*)d_in[17];
    const float* off_w2 = (const float*)d_in[18]; const float* off_b2 = (const float*)d_in[19];
    const float* co_w2  = (const float*)d_in[20]; const float* co_b2  = (const float*)d_in[21];
    const float* dcn_w2 = (const float*)d_in[22]; const float* dcn_b2 = (const float*)d_in[23];
    const float* ch_w0  = (const float*)d_in[24]; const float* ch_b0  = (const float*)d_in[25];
    const float* ft_w0  = (const float*)d_in[26]; const float* ft_b0  = (const float*)d_in[27];
    const float* ch_w1  = (const float*)d_in[28]; const float* ch_b1  = (const float*)d_in[29];
    const float* ft_w1  = (const float*)d_in[30]; const float* ft_b1  = (const float*)d_in[31];

    uint32_t* XH;
    __half* Ah;
    float *om0, *om1, *om2;
    cudaGetSymbolAddress((void**)&XH, g_XH);
    cudaGetSymbolAddress((void**)&Ah, g_Ah);
    cudaGetSymbolAddress((void**)&om0, g_om0);
    cudaGetSymbolAddress((void**)&om1, g_om1);
    cudaGetSymbolAddress((void**)&om2, g_om2);

    cudaFuncSetAttribute(gemm_tap,   cudaFuncAttributeMaxDynamicSharedMemorySize, GEMM_SMEM);
    cudaFuncSetAttribute(gemm_tap64, cudaFuncAttributeMaxDynamicSharedMemorySize, GEMM64_SMEM);
    cudaFuncSetAttribute(gemm_mma,   cudaFuncAttributeMaxDynamicSharedMemorySize, GEMM_SMEM);
    cudaFuncSetAttribute(gemm_mma64, cudaFuncAttributeMaxDynamicSharedMemorySize, GEMM64_SMEM);

    float* out0 = (float*)d_out;
    float* out1 = out0 + 4L * 64 * 128 * 128;
    float* out2 = out1 + 4L * 128 * 64 * 64;

    const int B = 4;
    cudaStream_t S0 = 0, S1 = g_s.s1, S2 = g_s.s2;

    auto XPOSE = [&](cudaStream_t st, long off, const float* s1, int c1, long bs1,
                     const float* s2, int c2, long bs2, int H, int W, int Cph) {
        dim3 grid((Cph + 31) / 32, (B * H * W) / 64);
        xpose<<<grid, 256, 0, st>>>(s1, c1, bs1, s2, c2, bs2, H, W, Cph, XH + off);
    };
    auto UP2XT = [&](cudaStream_t st, long off, const float* src, int C,
                     int Hs, int Ws) {
        int Cph = C / 2;
        dim3 grid(Cph / 32, (B * 4 * Hs * Ws) / 64);
        up2_xt<<<grid, 256, 0, st>>>(src, C, Hs, Ws, Cph, XH + off);
    };
    auto GTAP = [&](cudaStream_t st, int slot, long off, const float* bias, float* out,
                    int Kp, int Cp, int Cout, int ocStride, int H, int W, int Mtiles,
                    long xtOff = -1, int xtCph = 0, int xtCpOff = 0) {
        dim3 grid((B * H * W) / 128, Mtiles);
        gemm_tap<<<grid, 256, GEMM_SMEM, st>>>(
            Ah + (long)slot * ASLOT, XH + off,
            bias, out, Kp, Cp, (Kp + 63) / 64, Cout, ocStride, H, W,
            xtOff >= 0 ? XH + xtOff : nullptr, xtCph, xtCpOff);
    };
    auto GTAP64 = [&](cudaStream_t st, int slot, long off, const float* bias, float* out,
                      int Kp, int Cp, int Cout, int ocStride, int H, int W,
                      long xtOff = -1, int xtCph = 0, int xtCpOff = 0) {
        dim3 grid((B * H * W) / 256);
        gemm_tap64<<<grid, 256, GEMM64_SMEM, st>>>(
            Ah + (long)slot * ASLOT, XH + off,
            bias, out, Kp, Cp, Kp / 32, Cout, ocStride, H, W,
            xtOff >= 0 ? XH + xtOff : nullptr, xtCph, xtCpOff);
    };
    auto GOLD = [&](cudaStream_t st, int slot, long off, const float* bias, float* out,
                    int Kp, int Cout, int ocStride, int HW, int Mtiles,
                    long xtOff = -1, int xtCph = 0, int xtCpOff = 0) {
        dim3 grid((B * HW) / 128, Mtiles);
        gemm_mma<<<grid, 256, GEMM_SMEM, st>>>(
            Ah + (long)slot * ASLOT, (const __half*)(XH + off),
            bias, out, Kp, Kp / 64, Cout, ocStride, HW,
            xtOff >= 0 ? XH + xtOff : nullptr, xtCph, xtCpOff);
    };
    auto GOLD64 = [&](cudaStream_t st, int slot, long off, const float* bias, float* out,
                      int Kp, int Cout, int ocStride, int HW,
                      long xtOff = -1, int xtCph = 0, int xtCpOff = 0) {
        dim3 grid((B * HW) / 256);
        gemm_mma64<<<grid, 256, GEMM64_SMEM, st>>>(
            Ah + (long)slot * ASLOT, (const __half*)(XH + off),
            bias, out, Kp, Kp / 32, Cout, ocStride, HW,
            xtOff >= 0 ? XH + xtOff : nullptr, xtCph, xtCpOff);
    };
    auto DCN = [&](cudaStream_t st, long off, const float* x, long xbs, const float* om,
                   int C, int H, int W) {
        int total = B * 72 * H * W;
        dcn_sample_bf<<<(total + 255) / 256, 256, 0, st>>>(
            x, xbs, om, (uint4*)(XH + off), C, H, W, total);
    };

    // ---- all weight conversions in ONE launch ----
    {
        WJobs jobs;
        auto J = [&](int i, const float* w, int M, int Cin, int Cp, int Kp, int Mp) {
            jobs.j[i] = WJob{w, (uint32_t*)(Ah + (long)i * ASLOT),
                             M, Cin, Cp, Kp, Mp * (Kp >> 1)};
        };
        J(0,  off_w2, 256, 514, 544, 4896, 256);
        J(1,  co_w2,  216, 256, 256, 2304, 256);
        J(2,  dcn_w2, 256, 256, 256, 2304, 256);
        J(3,  off_w1, 128, 258, 288, 2592, 128);
        J(4,  co_w1,  216, 128, 128, 1152, 256);
        J(5,  dcn_w1, 128, 128, 128, 1152, 128);
        J(6,  off_w0, 64,  130, 160, 1440, 64);
        J(7,  co_w0,  216, 64,  64,  576,  256);
        J(8,  dcn_w0, 64,  64,  64,  576,  64);
        J(9,  ch_w1,  128, 256, 256, 2304, 128);
        J(10, ft_w1,  128, 256, 256, 2304, 128);
        J(11, ch_w0,  64,  128, 128, 1152, 64);
        J(12, ft_w0,  64,  128, 128, 1152, 64);
        int maxBlocks = (256 * (4896 >> 1) + 255) / 256;
        wconv_all<<<dim3(maxBlocks, 13), 256, 0, S0>>>(jobs);
    }

    // ---- fork ----
    cudaEventRecord(g_s.eF, S0);
    cudaStreamWaitEvent(S1, g_s.eF, 0);
    cudaStreamWaitEvent(S2, g_s.eF, 0);

    // ---- s1: level 0 off/co/dcn chain (128x128) ----
    {
        const int H = 128, W = 128, HW = H * W;
        XPOSE(S1, O_XT0A, x0, 128, 128L * HW, flow0, 2, 2L * HW, H, W, 80);
        GTAP64(S1, 6, O_XT0A, off_b0, nullptr, 1440, 160, 64, 64, H, W,
               O_XT0B, 32, 0);
        GTAP(S1, 7, O_XT0B, co_b0, om0, 576, 64, 216, 216, H, W, 2);
        DCN(S1, O_SAMP0, x0 + 64L * HW, 128L * HW, om0, 64, H, W);
        GOLD64(S1, 8, O_SAMP0, dcn_b0, nullptr, 576, 64, 128, HW,
               O_XTF0, 64, 0);
        cudaEventRecord(g_s.eL0, S1);
    }

    // ---- s2: level 1 off/co/dcn chain (64x64) ----
    {
        const int H = 64, W = 64, HW = H * W;
        XPOSE(S2, O_XT1A, x1, 256, 256L * HW, flow1, 2, 2L * HW, H, W, 144);
        GTAP(S2, 3, O_XT1A, off_b1, nullptr, 2592, 288, 128, 128, H, W, 1,
             O_XT1B, 64, 0);
        GTAP(S2, 4, O_XT1B, co_b1, om1, 1152, 128, 216, 216, H, W, 2);
        DCN(S2, O_SAMP1, x1 + 128L * HW, 256L * HW, om1, 128, H, W);
        GOLD(S2, 5, O_SAMP1, dcn_b1, nullptr, 1152, 128, 256, HW, 1,
             O_XTF1, 128, 0);
        cudaEventRecord(g_s.eL1, S2);
    }

    // ---- origin: level 2 chain (32x32) + fusion cascade ----
    {
        const int H = 32, W = 32, HW = H * W;
        XPOSE(S0, O_XT2A, x2, 512, 512L * HW, flow2, 2, 2L * HW, H, W, 272);
        GTAP(S0, 0, O_XT2A, off_b2, nullptr, 4896, 544, 256, 256, H, W, 2,
             O_XT2B, 128, 0);
        GTAP(S0, 1, O_XT2B, co_b2, om2, 2304, 256, 216, 216, H, W, 2);
        DCN(S0, O_SAMP2, x2 + 256L * HW, 512L * HW, om2, 256, H, W);
        GOLD(S0, 2, O_SAMP2, dcn_b2, out2, 2304, 256, 256, HW, 2);
        UP2XT(S0, O_XTU1, out2, 256, H, W);
    }
    {   // level 1 fusion (64x64)
        const int H = 64, W = 64, HW = H * W;
        GTAP(S0, 9, O_XTU1, ch_b1, nullptr, 2304, 256, 128, 256, H, W, 1,
             O_XTF1, 128, 64);
        cudaStreamWaitEvent(S0, g_s.eL1, 0);
        GTAP(S0, 10, O_XTF1, ft_b1, out1, 2304, 256, 128, 128, H, W, 1);
        UP2XT(S0, O_XTU0, out1, 128, H, W);
    }
    {   // level 0 fusion (128x128)
        const int H = 128, W = 128, HW = H * W;
        GTAP64(S0, 11, O_XTU0, ch_b0, nullptr, 1152, 128, 64, 128, H, W,
               O_XTF0, 64, 32);
        cudaStreamWaitEvent(S0, g_s.eL0, 0);
        GTAP64(S0, 12, O_XTF0, ft_b0, out0, 1152, 128, 64, 64, H, W);
    }
}

// round 17
// speedup vs baseline: 1.0817x; 1.0817x over previous
#include <cuda_runtime.h>
#include <cuda_fp16.h>
#include <math.h>
#include <stdint.h>

// ===========================================================================
// MotionCompensationBlock — HMMA fp16, implicit-tap GEMM
// Round 17: R15 geometry (K-chunk 32, LROW 40) + 4-stage pipeline, WAIT(2)
// ===========================================================================

__device__ __forceinline__ uint32_t smem_u32(const void* p) {
    uint32_t a;
    asm("{ .reg .u64 t; cvta.to.shared.u64 t, %1; cvt.u32.u64 %0, t; }" : "=r"(a) : "l"(p));
    return a;
}

#define CP16(dst, src) \
    asm volatile("cp.async.cg.shared.global [%0], [%1], 16;" :: "r"(dst), "l"(src) : "memory")
#define CP_COMMIT() asm volatile("cp.async.commit_group;" ::: "memory")
#define CP_WAIT(n)  asm volatile("cp.async.wait_group %0;" :: "n"(n) : "memory")
#define ZSTS16(addr) \
    asm volatile("st.shared.v4.b32 [%0], {%1,%1,%1,%1};" :: "r"(addr), "r"(0u) : "memory")

#define LDSM4(r, addr) \
    asm volatile("ldmatrix.sync.aligned.m8n8.x4.shared.b16 {%0,%1,%2,%3}, [%4];" \
                 : "=r"((r)[0]), "=r"((r)[1]), "=r"((r)[2]), "=r"((r)[3]) : "r"(addr))

__device__ __forceinline__ void mma16816(float* c, const uint32_t* a,
                                         uint32_t b0, uint32_t b1) {
    asm volatile(
        "mma.sync.aligned.m16n8k16.row.col.f32.f16.f16.f32 "
        "{%0,%1,%2,%3}, {%4,%5,%6,%7}, {%8,%9}, {%0,%1,%2,%3};"
        : "+f"(c[0]), "+f"(c[1]), "+f"(c[2]), "+f"(c[3])
        : "r"(a[0]), "r"(a[1]), "r"(a[2]), "r"(a[3]), "r"(b0), "r"(b1));
}

__device__ __forceinline__ uint32_t pack_h2(float v0, float v1) {
    __half2 hp = __halves2half2(__float2half(v0), __float2half(v1));
    return *(uint32_t*)&hp;
}

// ------------------------------ pools --------------------------------------
#define POOL_U32 (68u << 20)
__device__ uint32_t g_XH[POOL_U32];
#define O_XT0A  (0L)
#define O_XT0B  (6L  << 20)
#define O_SAMP0 (9L  << 20)
#define O_XT1A  (28L << 20)
#define O_XT1B  (31L << 20)
#define O_SAMP1 (33L << 20)
#define O_XT2A  (43L << 20)
#define O_XT2B  (45L << 20)
#define O_SAMP2 (46L << 20)
#define O_XTU1  (51L << 20)
#define O_XTF1  (54L << 20)
#define O_XTU0  (57L << 20)
#define O_XTF0  (62L << 20)

#define ASLOT 1253376
__device__ __half g_Ah[13L * ASLOT];
__device__ float g_om0[14155776], g_om1[3538944], g_om2[884736];

// ------------------------------ streams ------------------------------------
struct MCStreams {
    cudaStream_t s1, s2;
    cudaEvent_t eF, eL0, eL1;
    MCStreams() {
        cudaStreamCreateWithFlags(&s1, cudaStreamNonBlocking);
        cudaStreamCreateWithFlags(&s2, cudaStreamNonBlocking);
        cudaEventCreateWithFlags(&eF,  cudaEventDisableTiming);
        cudaEventCreateWithFlags(&eL0, cudaEventDisableTiming);
        cudaEventCreateWithFlags(&eL1, cudaEventDisableTiming);
    }
};
static MCStreams g_s;

// ---------------------------------------------------------------------------
// xpose: NCHW fp32 (dual-source concat) -> Xt[n][c] fp16 pairs
// ---------------------------------------------------------------------------
__global__ void __launch_bounds__(256)
xpose(const float* __restrict__ s1, int c1, long bs1,
      const float* __restrict__ s2, int c2, long bs2,
      int H, int W, int Cph, uint32_t* __restrict__ Xh)
{
    __shared__ uint32_t sh[32][65];
    __shared__ int sp_b[64], sp_p[64];

    const int tid = threadIdx.x;
    const int cc0 = blockIdx.x * 32;
    const long n0 = (long)blockIdx.y * 64;
    const int HW = H * W;

    if (tid < 64) {
        long n = n0 + tid;
        int b = (int)(n / HW);
        sp_b[tid] = b;
        sp_p[tid] = (int)(n - (long)b * HW);
    }
    __syncthreads();

    const int Cin = c1 + c2;
#pragma unroll
    for (int e = tid; e < 2048; e += 256) {
        const int p = e & 63, cc = e >> 6;
        const int c = (cc0 + cc) * 2;
        float v0 = 0.f, v1 = 0.f;
        const int b = sp_b[p];
        const int sp = sp_p[p];
        if (c < c1)          v0 = s1[(long)b * bs1 + (long)c * HW + sp];
        else if (c < Cin)    v0 = s2[(long)b * bs2 + (long)(c - c1) * HW + sp];
        const int cn = c + 1;
        if (cn < c1)         v1 = s1[(long)b * bs1 + (long)cn * HW + sp];
        else if (cn < Cin)   v1 = s2[(long)b * bs2 + (long)(cn - c1) * HW + sp];
        sh[cc][p] = pack_h2(v0, v1);
    }
    __syncthreads();

#pragma unroll
    for (int e = tid; e < 2048; e += 256) {
        const int kk = e & 31, p = e >> 5;
        if (cc0 + kk < Cph)
            Xh[(n0 + p) * Cph + cc0 + kk] = sh[kk][p];
    }
}

// ---------------------------------------------------------------------------
// up2_xt: fused bilinear 2x upsample + transpose to Xt[n][c] fp16
// ---------------------------------------------------------------------------
__global__ void __launch_bounds__(256)
up2_xt(const float* __restrict__ src, int C, int Hs, int Ws, int Cph,
       uint32_t* __restrict__ Xh)
{
    __shared__ uint32_t sh[32][65];
    __shared__ int sb[64], si0[64], si1[64], si2[64], si3[64];
    __shared__ float swy[64], swx[64];

    const int tid = threadIdx.x;
    const int cc0 = blockIdx.x * 32;
    const long n0 = (long)blockIdx.y * 64;
    const int W2 = 2 * Ws, H2 = 2 * Hs;
    const int HW2 = H2 * W2;
    const int HWs = Hs * Ws;

    if (tid < 64) {
        long n = n0 + tid;
        int b = (int)(n / HW2);
        int p2 = (int)(n - (long)b * HW2);
        int oy = p2 / W2, ox = p2 % W2;
        float sy = fmaxf(oy * 0.5f - 0.25f, 0.f);
        float sx = fmaxf(ox * 0.5f - 0.25f, 0.f);
        int y0 = (int)floorf(sy); float ty = sy - (float)y0;
        int y1 = min(y0 + 1, Hs - 1);
        int x0 = (int)floorf(sx); float tx = sx - (float)x0;
        int x1 = min(x0 + 1, Ws - 1);
        sb[tid] = b;
        si0[tid] = y0 * Ws + x0; si1[tid] = y0 * Ws + x1;
        si2[tid] = y1 * Ws + x0; si3[tid] = y1 * Ws + x1;
        swy[tid] = ty; swx[tid] = tx;
    }
    __syncthreads();

#pragma unroll
    for (int e = tid; e < 2048; e += 256) {
        const int p = e & 63, cc = e >> 6;
        const int c = (cc0 + cc) * 2;
        const float ty = swy[p], tx = swx[p];
        const int i0 = si0[p], i1 = si1[p], i2 = si2[p], i3 = si3[p];
        const float* pc = src + ((long)sb[p] * C + c) * HWs;
        float a0 = pc[i0] * (1.f - ty) + pc[i2] * ty;
        float a1 = pc[i1] * (1.f - ty) + pc[i3] * ty;
        float v0 = a0 * (1.f - tx) + a1 * tx;
        const float* pd = pc + HWs;
        float b0 = pd[i0] * (1.f - ty) + pd[i2] * ty;
        float b1 = pd[i1] * (1.f - ty) + pd[i3] * ty;
        float v1 = b0 * (1.f - tx) + b1 * tx;
        sh[cc][p] = pack_h2(v0, v1);
    }
    __syncthreads();

#pragma unroll
    for (int e = tid; e < 2048; e += 256) {
        const int kk = e & 31, p = e >> 5;
        Xh[(n0 + p) * Cph + cc0 + kk] = sh[kk][p];
    }
}

// ---------------------------------------------------------------------------
// Fused weight convert (fp16)
// ---------------------------------------------------------------------------
struct WJob {
    const float* w;
    uint32_t* Ah;
    int M, Cin, Cp, Kp, total;
};
struct WJobs { WJob j[13]; };

__global__ void __launch_bounds__(256)
wconv_all(WJobs jobs)
{
    const WJob jb = jobs.j[blockIdx.y];
    int idx = blockIdx.x * 256 + threadIdx.x;
    if (idx >= jb.total) return;
    const int Kh = jb.Kp >> 1;
    const int kk = idx % Kh;
    const int m  = idx / Kh;
    const int k0 = kk * 2;
    const int t = k0 / jb.Cp, c = k0 - t * jb.Cp;
    float v0 = 0.f, v1 = 0.f;
    if (m < jb.M && t < 9) {
        if (c < jb.Cin)     v0 = jb.w[((long)m * jb.Cin + c) * 9 + t];
        if (c + 1 < jb.Cin) v1 = jb.w[((long)m * jb.Cin + c + 1) * 9 + t];
    }
    jb.Ah[idx] = pack_h2(v0, v1);
}

// ===========================================================================
// GEMM geometry: K-chunk 32, LROW 40, 4-stage pipeline (CP_WAIT(2))
// ===========================================================================
#define LROW 40
#define PLANE_B (128 * LROW * 2)           // 10240 B
#define STG2_B (2 * PLANE_B)               // 20480 B
#define GEMM_SMEM (4 * STG2_B)             // 81920 B (>= epi 68096)

#define APL64_B (64 * LROW * 2)            // 5120 B
#define BPL64_B (256 * LROW * 2)           // 20480 B
#define STG64_B (APL64_B + BPL64_B)        // 25600 B
#define GEMM64_SMEM (4 * STG64_B)          // 102400 B (>= epi 66816)

#define MMA_BODY1(stgA, stgB)                                                  \
    _Pragma("unroll")                                                          \
    for (int s = 0; s < 2; s++) {                                              \
        const uint32_t cofs = (uint32_t)(s * 32);                              \
        uint32_t afh[4][4], bfh[2][4];                                         \
        _Pragma("unroll")                                                      \
        for (int mt = 0; mt < 4; mt++)                                         \
            LDSM4(afh[mt], (stgA) + aoff[mt] + cofs);                          \
        _Pragma("unroll")                                                      \
        for (int np = 0; np < 2; np++)                                         \
            LDSM4(bfh[np], (stgB) + boff[np] + cofs);                          \
        _Pragma("unroll")                                                      \
        for (int mt = 0; mt < 4; mt++)                                         \
            _Pragma("unroll")                                                  \
            for (int nt = 0; nt < 4; nt++) {                                   \
                const uint32_t* bh = &bfh[nt >> 1][(nt & 1) * 2];              \
                mma16816(acc[mt][nt], afh[mt], bh[0], bh[1]);                  \
            }                                                                  \
    }

#define EPI_FP32_128()                                                         \
    {                                                                          \
        const int bIdx = p0 / HW, prow0 = p0 % HW;                             \
        _Pragma("unroll")                                                      \
        for (int mt = 0; mt < 4; mt++) {                                       \
            const int oca = m0 + wm * 64 + mt * 16 + g;                        \
            const int ocb = oca + 8;                                           \
            const float ba = (oca < Cout) ? bias[oca] : 0.f;                   \
            const float bb = (ocb < Cout) ? bias[ocb] : 0.f;                   \
            _Pragma("unroll")                                                  \
            for (int nt = 0; nt < 4; nt++) {                                   \
                const int pc = prow0 + wn * 32 + nt * 8 + 2 * t;               \
                if (oca < Cout) {                                              \
                    float2 v = make_float2(acc[mt][nt][0] + ba, acc[mt][nt][1] + ba); \
                    *(float2*)&out[((long)bIdx * ocStride + oca) * HW + pc] = v; \
                }                                                              \
                if (ocb < Cout) {                                              \
                    float2 v = make_float2(acc[mt][nt][2] + bb, acc[mt][nt][3] + bb); \
                    *(float2*)&out[((long)bIdx * ocStride + ocb) * HW + pc] = v; \
                }                                                              \
            }                                                                  \
        }                                                                      \
    }

#define EPI_XT_128()                                                           \
    {                                                                          \
        float* sf = (float*)sm;                                                \
        _Pragma("unroll")                                                      \
        for (int mt = 0; mt < 4; mt++) {                                       \
            const int ra = wm * 64 + mt * 16 + g;                              \
            const float ba = bias[m0 + ra];                                    \
            const float bb = bias[m0 + ra + 8];                                \
            _Pragma("unroll")                                                  \
            for (int nt = 0; nt < 4; nt++) {                                   \
                const int pc = wn * 32 + nt * 8 + 2 * t;                       \
                sf[ra * 133 + pc]           = acc[mt][nt][0] + ba;             \
                sf[ra * 133 + pc + 1]       = acc[mt][nt][1] + ba;             \
                sf[(ra + 8) * 133 + pc]     = acc[mt][nt][2] + bb;             \
                sf[(ra + 8) * 133 + pc + 1] = acc[mt][nt][3] + bb;             \
            }                                                                  \
        }                                                                      \
        __syncthreads();                                                       \
        const int cpBase = xtCpOff + (m0 >> 1);                                \
        for (int e = tid; e < 8192; e += 256) {                                \
            const int cp = e & 63, px = e >> 6;                                \
            xtH[(long)(p0 + px) * xtCph + cpBase + cp] =                       \
                pack_h2(sf[(2 * cp) * 133 + px], sf[(2 * cp + 1) * 133 + px]); \
        }                                                                      \
    }

#define EPI_FP32_64()                                                          \
    {                                                                          \
        const int bIdx = p0 / HW, prow0 = p0 % HW;                             \
        _Pragma("unroll")                                                      \
        for (int mt = 0; mt < 4; mt++) {                                       \
            const int oca = mt * 16 + g;                                       \
            const int ocb = oca + 8;                                           \
            const float ba = (oca < Cout) ? bias[oca] : 0.f;                   \
            const float bb = (ocb < Cout) ? bias[ocb] : 0.f;                   \
            _Pragma("unroll")                                                  \
            for (int nt = 0; nt < 4; nt++) {                                   \
                const int pc = prow0 + wn * 32 + nt * 8 + 2 * t;               \
                if (oca < Cout) {                                              \
                    float2 v = make_float2(acc[mt][nt][0] + ba, acc[mt][nt][1] + ba); \
                    *(float2*)&out[((long)bIdx * ocStride + oca) * HW + pc] = v; \
                }                                                              \
                if (ocb < Cout) {                                              \
                    float2 v = make_float2(acc[mt][nt][2] + bb, acc[mt][nt][3] + bb); \
                    *(float2*)&out[((long)bIdx * ocStride + ocb) * HW + pc] = v; \
                }                                                              \
            }                                                                  \
        }                                                                      \
    }

#define EPI_XT_64()                                                            \
    {                                                                          \
        float* sf = (float*)sm;                                                \
        _Pragma("unroll")                                                      \
        for (int mt = 0; mt < 4; mt++) {                                       \
            const int ra = mt * 16 + g;                                        \
            const float ba = bias[ra];                                         \
            const float bb = bias[ra + 8];                                     \
            _Pragma("unroll")                                                  \
            for (int nt = 0; nt < 4; nt++) {                                   \
                const int pc = wn * 32 + nt * 8 + 2 * t;                       \
                sf[ra * 261 + pc]           = acc[mt][nt][0] + ba;             \
                sf[ra * 261 + pc + 1]       = acc[mt][nt][1] + ba;             \
                sf[(ra + 8) * 261 + pc]     = acc[mt][nt][2] + bb;             \
                sf[(ra + 8) * 261 + pc + 1] = acc[mt][nt][3] + bb;             \
            }                                                                  \
        }                                                                      \
        __syncthreads();                                                       \
        for (int e = tid; e < 8192; e += 256) {                                \
            const int cp = e & 31, px = e >> 5;                                \
            xtH[(long)(p0 + px) * xtCph + xtCpOff + cp] =                      \
                pack_h2(sf[(2 * cp) * 261 + px], sf[(2 * cp + 1) * 261 + px]); \
        }                                                                      \
    }

// 4-stage loop skeleton (CP_WAIT(2): two chunk-gathers in flight)
#define PIPE4_LOOP(STAGEFN, ADVANCE, MMAEXP)                                   \
    STAGEFN(0);                                                                \
    CP_COMMIT();                                                               \
    ADVANCE;                                                                   \
    if (nchunks > 1) { STAGEFN(1); }                                           \
    CP_COMMIT();                                                               \
    ADVANCE;                                                                   \
    if (nchunks > 2) { STAGEFN(2); }                                           \
    CP_COMMIT();                                                               \
    ADVANCE;                                                                   \
    for (int ci = 0; ci < nchunks; ci++) {                                     \
        CP_WAIT(2);                                                            \
        __syncthreads();                                                       \
        if (ci + 3 < nchunks) { STAGEFN((ci + 3) & 3); ADVANCE; }              \
        CP_COMMIT();                                                           \
        const uint32_t stg = smb + (uint32_t)(ci & 3) * stageBytes;            \
        MMAEXP                                                                 \
    }                                                                          \
    __syncthreads();

// ---------------------------------------------------------------------------
// gemm_tap: M128 x N128, implicit-tap B staging from compact Xt[n][Cp]
// ---------------------------------------------------------------------------
__global__ void __launch_bounds__(256, 2)
gemm_tap(const __half* __restrict__ Ahi,
         const uint32_t* __restrict__ Xh,
         const float* __restrict__ bias, float* __restrict__ out,
         int Kp, int Cp, int nchunks, int Cout, int ocStride, int H, int W,
         uint32_t* xtH, int xtCph, int xtCpOff)
{
    extern __shared__ __half sm[];
    const uint32_t stageBytes = STG2_B;

    const int tid = threadIdx.x, wid = tid >> 5, lane = tid & 31;
    const int g = lane >> 2, t = lane & 3;
    const int wm = wid >> 2, wn = wid & 3;
    const int HW = H * W;

    const int p0 = blockIdx.x * 128;
    const int m0 = blockIdx.y * 128;

    float acc[4][4][4];
#pragma unroll
    for (int i = 0; i < 4; i++)
#pragma unroll
        for (int j = 0; j < 4; j++)
#pragma unroll
            for (int k = 0; k < 4; k++) acc[i][j][k] = 0.f;

    const uint32_t smb = smem_u32(sm);
    const int r0 = tid >> 1, s0 = (tid & 1) * 2;   // 128 rows x 2 slots of 4

    // NOTE: r0 covers 0..127 once; each thread stages 2 16B slots of A and B
    const int rA0 = tid >> 2, sA0 = tid & 3;       // A: 4 slots over 256 thr? keep R15 mapping

    // R15 staging mapping: r = tid>>2 (0..63) + 64 offset; s = tid&3
    const int rr0 = tid >> 2, ss0 = tid & 3;
    const int rr1 = rr0 + 64;

    int b0r, y0r, x0r, b1r, y1r, x1r;
    {
        int n = p0 + rr0; b0r = n / HW; int p = n - b0r * HW; y0r = p / W; x0r = p - y0r * W;
        n = p0 + rr1; b1r = n / HW; p = n - b1r * HW; y1r = p / W; x1r = p - y1r * W;
    }

    uint32_t aoff[4], boff[2];
    {
        const int arow = (lane & 7) + ((lane >> 3) & 1) * 8;
        const int acol = (lane >> 4) * 8;
#pragma unroll
        for (int mt = 0; mt < 4; mt++)
            aoff[mt] = (uint32_t)(((wm * 64 + mt * 16 + arow) * LROW + acol) * 2);
        const int brow = (lane & 7) + (lane >> 4) * 8;
        const int bcol = ((lane >> 3) & 1) * 8;
#pragma unroll
        for (int np = 0; np < 2; np++)
            boff[np] = (uint32_t)(((wn * 32 + np * 16 + brow) * LROW + bcol) * 2);
    }

    const char* XhB = (const char*)Xh;
    const long rowB = (long)Cp * 2;

    int tP = 0, kinP = 0;
    auto stage = [&](int buf) {
        const long kc = (long)tP * Cp + kinP;
        const uint32_t bufb = smb + (uint32_t)buf * STG2_B;
        CP16(bufb + rr0 * 80 + ss0 * 16, Ahi + (long)(m0 + rr0) * Kp + kc + ss0 * 8);
        CP16(bufb + rr1 * 80 + ss0 * 16, Ahi + (long)(m0 + rr1) * Kp + kc + ss0 * 8);
        const int q = tP / 3;
        const int dy = q - 1, dx = tP - 3 * q - 1;
        const long cb = (long)kinP * 2;
        {
            const int yy = y0r + dy, xx = x0r + dx;
            const uint32_t dH = bufb + PLANE_B + rr0 * 80 + ss0 * 16;
            if ((unsigned)yy < (unsigned)H && (unsigned)xx < (unsigned)W)
                CP16(dH, XhB + ((long)b0r * HW + yy * W + xx) * rowB + cb + ss0 * 16);
            else ZSTS16(dH);
        }
        {
            const int yy = y1r + dy, xx = x1r + dx;
            const uint32_t dH = bufb + PLANE_B + rr1 * 80 + ss0 * 16;
            if ((unsigned)yy < (unsigned)H && (unsigned)xx < (unsigned)W)
                CP16(dH, XhB + ((long)b1r * HW + yy * W + xx) * rowB + cb + ss0 * 16);
            else ZSTS16(dH);
        }
    };

#define ADV { kinP += 32; if (kinP == Cp) { kinP = 0; tP++; } }
    PIPE4_LOOP(stage, ADV, MMA_BODY1(stg, stg + PLANE_B))
#undef ADV

    if (xtH) EPI_XT_128()
    else     EPI_FP32_128()
}

// ---------------------------------------------------------------------------
// gemm_tap64: M64 x N256, implicit-tap B staging (Cout <= 64)
// ---------------------------------------------------------------------------
__global__ void __launch_bounds__(256, 2)
gemm_tap64(const __half* __restrict__ Ahi,
           const uint32_t* __restrict__ Xh,
           const float* __restrict__ bias, float* __restrict__ out,
           int Kp, int Cp, int nchunks, int Cout, int ocStride, int H, int W,
           uint32_t* xtH, int xtCph, int xtCpOff)
{
    extern __shared__ __half sm[];
    const uint32_t stageBytes = STG64_B;

    const int tid = threadIdx.x, wid = tid >> 5, lane = tid & 31;
    const int g = lane >> 2, t = lane & 3;
    const int wn = wid;
    const int HW = H * W;

    const int p0 = blockIdx.x * 256;

    float acc[4][4][4];
#pragma unroll
    for (int i = 0; i < 4; i++)
#pragma unroll
        for (int j = 0; j < 4; j++)
#pragma unroll
            for (int k = 0; k < 4; k++) acc[i][j][k] = 0.f;

    const uint32_t smb = smem_u32(sm);
    const int rA = tid >> 2, sA = tid & 3;

    int b4[4], y4[4], x4[4];
#pragma unroll
    for (int j = 0; j < 4; j++) {
        int n = p0 + rA + 64 * j;
        b4[j] = n / HW;
        int p = n - b4[j] * HW;
        y4[j] = p / W;
        x4[j] = p - y4[j] * W;
    }

    uint32_t aoff[4], boff[2];
    {
        const int arow = (lane & 7) + ((lane >> 3) & 1) * 8;
        const int acol = (lane >> 4) * 8;
#pragma unroll
        for (int mt = 0; mt < 4; mt++)
            aoff[mt] = (uint32_t)(((mt * 16 + arow) * LROW + acol) * 2);
        const int brow = (lane & 7) + (lane >> 4) * 8;
        const int bcol = ((lane >> 3) & 1) * 8;
#pragma unroll
        for (int np = 0; np < 2; np++)
            boff[np] = (uint32_t)(((wn * 32 + np * 16 + brow) * LROW + bcol) * 2);
    }

    const char* XhB = (const char*)Xh;
    const long rowB = (long)Cp * 2;

    int tP = 0, kinP = 0;
    auto stage = [&](int buf) {
        const long kc = (long)tP * Cp + kinP;
        const uint32_t bufb = smb + (uint32_t)buf * STG64_B;
        CP16(bufb + rA * 80 + sA * 16, Ahi + (long)rA * Kp + kc + sA * 8);
        const int q = tP / 3;
        const int dy = q - 1, dx = tP - 3 * q - 1;
        const long cb = (long)kinP * 2;
        const uint32_t bB = bufb + APL64_B;
#pragma unroll
        for (int j = 0; j < 4; j++) {
            const int r = rA + 64 * j;
            const int yy = y4[j] + dy, xx = x4[j] + dx;
            const uint32_t dH = bB + r * 80 + sA * 16;
            if ((unsigned)yy < (unsigned)H && (unsigned)xx < (unsigned)W)
                CP16(dH, XhB + ((long)b4[j] * HW + yy * W + xx) * rowB + cb + sA * 16);
            else ZSTS16(dH);
        }
    };

#define ADV { kinP += 32; if (kinP == Cp) { kinP = 0; tP++; } }
    PIPE4_LOOP(stage, ADV, MMA_BODY1(stg, stg + APL64_B))
#undef ADV

    if (xtH) EPI_XT_64()
    else     EPI_FP32_64()
}

// ---------------------------------------------------------------------------
// gemm_mma / gemm_mma64: direct-B (DCN GEMMs)
// ---------------------------------------------------------------------------
__global__ void __launch_bounds__(256, 2)
gemm_mma(const __half* __restrict__ Ahi,
         const __half* __restrict__ Bhi,
         const float* __restrict__ bias, float* __restrict__ out,
         int Kp, int nchunks, int Cout, int ocStride, int HW,
         uint32_t* xtH, int xtCph, int xtCpOff)
{
    extern __shared__ __half sm[];
    const uint32_t stageBytes = STG2_B;

    const int tid = threadIdx.x, wid = tid >> 5, lane = tid & 31;
    const int g = lane >> 2, t = lane & 3;
    const int wm = wid >> 2, wn = wid & 3;

    const int p0 = blockIdx.x * 128;
    const int m0 = blockIdx.y * 128;

    float acc[4][4][4];
#pragma unroll
    for (int i = 0; i < 4; i++)
#pragma unroll
        for (int j = 0; j < 4; j++)
#pragma unroll
            for (int k = 0; k < 4; k++) acc[i][j][k] = 0.f;

    const uint32_t smb = smem_u32(sm);
    const int rr0 = tid >> 2, ss0 = tid & 3;
    const int rr1 = rr0 + 64;

    uint32_t aoff[4], boff[2];
    {
        const int arow = (lane & 7) + ((lane >> 3) & 1) * 8;
        const int acol = (lane >> 4) * 8;
#pragma unroll
        for (int mt = 0; mt < 4; mt++)
            aoff[mt] = (uint32_t)(((wm * 64 + mt * 16 + arow) * LROW + acol) * 2);
        const int brow = (lane & 7) + (lane >> 4) * 8;
        const int bcol = ((lane >> 3) & 1) * 8;
#pragma unroll
        for (int np = 0; np < 2; np++)
            boff[np] = (uint32_t)(((wn * 32 + np * 16 + brow) * LROW + bcol) * 2);
    }

    int ciP = 0;
    auto stage = [&](int buf) {
        const long kc = (long)ciP * 32;
        const uint32_t bufb = smb + (uint32_t)buf * STG2_B;
        CP16(bufb + rr0 * 80 + ss0 * 16, Ahi + (long)(m0 + rr0) * Kp + kc + ss0 * 8);
        CP16(bufb + rr1 * 80 + ss0 * 16, Ahi + (long)(m0 + rr1) * Kp + kc + ss0 * 8);
        CP16(bufb + PLANE_B + rr0 * 80 + ss0 * 16, Bhi + (long)(p0 + rr0) * Kp + kc + ss0 * 8);
        CP16(bufb + PLANE_B + rr1 * 80 + ss0 * 16, Bhi + (long)(p0 + rr1) * Kp + kc + ss0 * 8);
    };

#define ADV { ciP++; }
    PIPE4_LOOP(stage, ADV, MMA_BODY1(stg, stg + PLANE_B))
#undef ADV

    if (xtH) EPI_XT_128()
    else     EPI_FP32_128()
}

__global__ void __launch_bounds__(256, 2)
gemm_mma64(const __half* __restrict__ Ahi,
           const __half* __restrict__ Bhi,
           const float* __restrict__ bias, float* __restrict__ out,
           int Kp, int nchunks, int Cout, int ocStride, int HW,
           uint32_t* xtH, int xtCph, int xtCpOff)
{
    extern __shared__ __half sm[];
    const uint32_t stageBytes = STG64_B;

    const int tid = threadIdx.x, wid = tid >> 5, lane = tid & 31;
    const int g = lane >> 2, t = lane & 3;
    const int wn = wid;

    const int p0 = blockIdx.x * 256;

    float acc[4][4][4];
#pragma unroll
    for (int i = 0; i < 4; i++)
#pragma unroll
        for (int j = 0; j < 4; j++)
#pragma unroll
            for (int k = 0; k < 4; k++) acc[i][j][k] = 0.f;

    const uint32_t smb = smem_u32(sm);
    const int rA = tid >> 2, sA = tid & 3;

    uint32_t aoff[4], boff[2];
    {
        const int arow = (lane & 7) + ((lane >> 3) & 1) * 8;
        const int acol = (lane >> 4) * 8;
#pragma unroll
        for (int mt = 0; mt < 4; mt++)
            aoff[mt] = (uint32_t)(((mt * 16 + arow) * LROW + acol) * 2);
        const int brow = (lane & 7) + (lane >> 4) * 8;
        const int bcol = ((lane >> 3) & 1) * 8;
#pragma unroll
        for (int np = 0; np < 2; np++)
            boff[np] = (uint32_t)(((wn * 32 + np * 16 + brow) * LROW + bcol) * 2);
    }

    int ciP = 0;
    auto stage = [&](int buf) {
        const long kc = (long)ciP * 32;
        const uint32_t bufb = smb + (uint32_t)buf * STG64_B;
        CP16(bufb + rA * 80 + sA * 16, Ahi + (long)rA * Kp + kc + sA * 8);
        const uint32_t bB = bufb + APL64_B;
#pragma unroll
        for (int j = 0; j < 4; j++) {
            const int task = tid + 256 * j;
            const int r = task >> 2, s = task & 3;
            CP16(bB + r * 80 + s * 16, Bhi + (long)(p0 + r) * Kp + kc + s * 8);
        }
    };

#define ADV { ciP++; }
    PIPE4_LOOP(stage, ADV, MMA_BODY1(stg, stg + APL64_B))
#undef ADV

    if (xtH) EPI_XT_64()
    else     EPI_FP32_64()
}

// ---------------------------------------------------------------------------
// DCN bilinear sampler (fp16)
// ---------------------------------------------------------------------------
__global__ void dcn_sample_bf(const float* __restrict__ x, long xbs,
                              const float* __restrict__ om,
                              uint4* __restrict__ Bh4,
                              int C, int H, int W, int total)
{
    int idx = blockIdx.x * blockDim.x + threadIdx.x;
    if (idx >= total) return;
    const int HW = H * W;
    const int p = idx % HW;
    const int k = (idx / HW) % 9;
    const int g = (idx / (HW * 9)) % 8;
    const int b = idx / (HW * 72);
    const int y = p / W, xq = p % W;

    const long omb = (long)b * 216 * HW + (long)(g * 9 + k) * HW + p;
    float dy = om[omb];
    float dx = om[omb + 72L * HW];
    float mk = om[omb + 144L * HW];
    mk = 1.f / (1.f + expf(-mk));

    float pyf = (float)y + (float)(k / 3 - 1) + dy;
    float pxf = (float)xq + (float)(k % 3 - 1) + dx;
    float y0f = floorf(pyf), x0f = floorf(pxf);
    int y0 = (int)y0f, x0i = (int)x0f;
    float ty = pyf - y0f, tx = pxf - x0f;
    int y1 = y0 + 1, x1i = x0i + 1;

    bool vy0 = (y0 >= 0) && (y0 < H), vy1 = (y1 >= 0) && (y1 < H);
    bool vx0 = (x0i >= 0) && (x0i < W), vx1 = (x1i >= 0) && (x1i < W);
    float w00 = (vy0 && vx0) ? (1.f - ty) * (1.f - tx) : 0.f;
    float w01 = (vy0 && vx1) ? (1.f - ty) * tx : 0.f;
    float w10 = (vy1 && vx0) ? ty * (1.f - tx) : 0.f;
    float w11 = (vy1 && vx1) ? ty * tx : 0.f;
    w00 *= mk; w01 *= mk; w10 *= mk; w11 *= mk;

    int cy0 = min(max(y0, 0), H - 1), cy1 = min(max(y1, 0), H - 1);
    int cx0 = min(max(x0i, 0), W - 1), cx1 = min(max(x1i, 0), W - 1);
    int i00 = cy0 * W + cx0, i01 = cy0 * W + cx1;
    int i10 = cy1 * W + cx0, i11 = cy1 * W + cx1;

    const int Cg = C >> 3;
    const int K = C * 9;
    const float* xb = x + (long)b * xbs + (long)g * Cg * HW;
    const long rowbase = ((long)b * HW + p) * K + (long)k * C + (long)g * Cg;
    const long o4 = rowbase >> 3;

    for (int cb = 0; cb < Cg; cb += 8) {
        uint32_t hv[4];
#pragma unroll
        for (int j = 0; j < 4; j++) {
            const float* xc0 = xb + (long)(cb + 2 * j) * HW;
            const float* xc1 = xc0 + HW;
            float v0 = w00 * xc0[i00] + w01 * xc0[i01] + w10 * xc0[i10] + w11 * xc0[i11];
            float v1 = w00 * xc1[i00] + w01 * xc1[i01] + w10 * xc1[i10] + w11 * xc1[i11];
            hv[j] = pack_h2(v0, v1);
        }
        Bh4[o4 + (cb >> 3)] = make_uint4(hv[0], hv[1], hv[2], hv[3]);
    }
}

// ---------------------------------------------------------------------------
extern "C" void kernel_launch(void* const* d_in, const int* in_sizes, int n_in,
                              void* d_out, int out_size)
{
    const float *x0 = nullptr, *x1 = nullptr, *x2 = nullptr;
    const float *flow0 = nullptr, *flow1 = nullptr, *flow2 = nullptr;
    for (int i = 0; i < 6; i++) {
        const float* p = (const float*)d_in[i];
        switch (in_sizes[i]) {
            case 4 * 2 * 64 * 128 * 128: x0 = p; break;
            case 4 * 2 * 128 * 64 * 64:  x1 = p; break;
            case 4 * 2 * 256 * 32 * 32:  x2 = p; break;
            case 4 * 2 * 128 * 128:      flow0 = p; break;
            case 4 * 2 * 64 * 64:        flow1 = p; break;
            case 4 * 2 * 32 * 32:        flow2 = p; break;
        }
    }
    const float* off_w0 = (const float*)d_in[6];  const float* off_b0 = (const float*)d_in[7];
    const float* co_w0  = (const float*)d_in[8];  const float* co_b0  = (const float*)d_in[9];
    const float* dcn_w0 = (const float*)d_in[10]; const float* dcn_b0 = (const float*)d_in[11];
    const float* off_w1 = (const float*)d_in[12]; const float* off_b1 = (const float*)d_in[13];
    const float* co_w1  = (const float*)d_in[14]; const float* co_b1  = (const float*)d_in[15];
    const float* dcn_w1 = (const float*)d_in[16]; const float* dcn_b1 = (const float*)d_in[17];
    const float* off_w2 = (const float*)d_in[18]; const float* off_b2 = (const float*)d_in[19];
    const float* co_w2  = (const float*)d_in[20]; const float* co_b2  = (const float*)d_in[21];
    const float* dcn_w2 = (const float*)d_in[22]; const float* dcn_b2 = (const float*)d_in[23];
    const float* ch_w0  = (const float*)d_in[24]; const float* ch_b0  = (const float*)d_in[25];
    const float* ft_w0  = (const float*)d_in[26]; const float* ft_b0  = (const float*)d_in[27];
    const float* ch_w1  = (const float*)d_in[28]; const float* ch_b1  = (const float*)d_in[29];
    const float* ft_w1  = (const float*)d_in[30]; const float* ft_b1  = (const float*)d_in[31];

    uint32_t* XH;
    __half* Ah;
    float *om0, *om1, *om2;
    cudaGetSymbolAddress((void**)&XH, g_XH);
    cudaGetSymbolAddress((void**)&Ah, g_Ah);
    cudaGetSymbolAddress((void**)&om0, g_om0);
    cudaGetSymbolAddress((void**)&om1, g_om1);
    cudaGetSymbolAddress((void**)&om2, g_om2);

    cudaFuncSetAttribute(gemm_tap,   cudaFuncAttributeMaxDynamicSharedMemorySize, GEMM_SMEM);
    cudaFuncSetAttribute(gemm_tap64, cudaFuncAttributeMaxDynamicSharedMemorySize, GEMM64_SMEM);
    cudaFuncSetAttribute(gemm_mma,   cudaFuncAttributeMaxDynamicSharedMemorySize, GEMM_SMEM);
    cudaFuncSetAttribute(gemm_mma64, cudaFuncAttributeMaxDynamicSharedMemorySize, GEMM64_SMEM);

    float* out0 = (float*)d_out;
    float* out1 = out0 + 4L * 64 * 128 * 128;
    float* out2 = out1 + 4L * 128 * 64 * 64;

    const int B = 4;
    cudaStream_t S0 = 0, S1 = g_s.s1, S2 = g_s.s2;

    auto XPOSE = [&](cudaStream_t st, long off, const float* s1, int c1, long bs1,
                     const float* s2, int c2, long bs2, int H, int W, int Cph) {
        dim3 grid((Cph + 31) / 32, (B * H * W) / 64);
        xpose<<<grid, 256, 0, st>>>(s1, c1, bs1, s2, c2, bs2, H, W, Cph, XH + off);
    };
    auto UP2XT = [&](cudaStream_t st, long off, const float* src, int C,
                     int Hs, int Ws) {
        int Cph = C / 2;
        dim3 grid(Cph / 32, (B * 4 * Hs * Ws) / 64);
        up2_xt<<<grid, 256, 0, st>>>(src, C, Hs, Ws, Cph, XH + off);
    };
    auto GTAP = [&](cudaStream_t st, int slot, long off, const float* bias, float* out,
                    int Kp, int Cp, int Cout, int ocStride, int H, int W, int Mtiles,
                    long xtOff = -1, int xtCph = 0, int xtCpOff = 0) {
        dim3 grid((B * H * W) / 128, Mtiles);
        gemm_tap<<<grid, 256, GEMM_SMEM, st>>>(
            Ah + (long)slot * ASLOT, XH + off,
            bias, out, Kp, Cp, Kp / 32, Cout, ocStride, H, W,
            xtOff >= 0 ? XH + xtOff : nullptr, xtCph, xtCpOff);
    };
    auto GTAP64 = [&](cudaStream_t st, int slot, long off, const float* bias, float* out,
                      int Kp, int Cp, int Cout, int ocStride, int H, int W,
                      long xtOff = -1, int xtCph = 0, int xtCpOff = 0) {
        dim3 grid((B * H * W) / 256);
        gemm_tap64<<<grid, 256, GEMM64_SMEM, st>>>(
            Ah + (long)slot * ASLOT, XH + off,
            bias, out, Kp, Cp, Kp / 32, Cout, ocStride, H, W,
            xtOff >= 0 ? XH + xtOff : nullptr, xtCph, xtCpOff);
    };
    auto GOLD = [&](cudaStream_t st, int slot, long off, const float* bias, float* out,
                    int Kp, int Cout, int ocStride, int HW, int Mtiles,
                    long xtOff = -1, int xtCph = 0, int xtCpOff = 0) {
        dim3 grid((B * HW) / 128, Mtiles);
        gemm_mma<<<grid, 256, GEMM_SMEM, st>>>(
            Ah + (long)slot * ASLOT, (const __half*)(XH + off),
            bias, out, Kp, Kp / 32, Cout, ocStride, HW,
            xtOff >= 0 ? XH + xtOff : nullptr, xtCph, xtCpOff);
    };
    auto GOLD64 = [&](cudaStream_t st, int slot, long off, const float* bias, float* out,
                      int Kp, int Cout, int ocStride, int HW,
                      long xtOff = -1, int xtCph = 0, int xtCpOff = 0) {
        dim3 grid((B * HW) / 256);
        gemm_mma64<<<grid, 256, GEMM64_SMEM, st>>>(
            Ah + (long)slot * ASLOT, (const __half*)(XH + off),
            bias, out, Kp, Kp / 32, Cout, ocStride, HW,
            xtOff >= 0 ? XH + xtOff : nullptr, xtCph, xtCpOff);
    };
    auto DCN = [&](cudaStream_t st, long off, const float* x, long xbs, const float* om,
                   int C, int H, int W) {
        int total = B * 72 * H * W;
        dcn_sample_bf<<<(total + 255) / 256, 256, 0, st>>>(
            x, xbs, om, (uint4*)(XH + off), C, H, W, total);
    };

    // ---- all weight conversions in ONE launch ----
    {
        WJobs jobs;
        auto J = [&](int i, const float* w, int M, int Cin, int Cp, int Kp, int Mp) {
            jobs.j[i] = WJob{w, (uint32_t*)(Ah + (long)i * ASLOT),
                             M, Cin, Cp, Kp, Mp * (Kp >> 1)};
        };
        J(0,  off_w2, 256, 514, 544, 4896, 256);
        J(1,  co_w2,  216, 256, 256, 2304, 256);
        J(2,  dcn_w2, 256, 256, 256, 2304, 256);
        J(3,  off_w1, 128, 258, 288, 2592, 128);
        J(4,  co_w1,  216, 128, 128, 1152, 256);
        J(5,  dcn_w1, 128, 128, 128, 1152, 128);
        J(6,  off_w0, 64,  130, 160, 1440, 64);
        J(7,  co_w0,  216, 64,  64,  576,  256);
        J(8,  dcn_w0, 64,  64,  64,  576,  64);
        J(9,  ch_w1,  128, 256, 256, 2304, 128);
        J(10, ft_w1,  128, 256, 256, 2304, 128);
        J(11, ch_w0,  64,  128, 128, 1152, 64);
        J(12, ft_w0,  64,  128, 128, 1152, 64);
        int maxBlocks = (256 * (4896 >> 1) + 255) / 256;
        wconv_all<<<dim3(maxBlocks, 13), 256, 0, S0>>>(jobs);
    }

    // ---- fork ----
    cudaEventRecord(g_s.eF, S0);
    cudaStreamWaitEvent(S1, g_s.eF, 0);
    cudaStreamWaitEvent(S2, g_s.eF, 0);

    // ---- s1: level 0 off/co/dcn chain (128x128) ----
    {
        const int H = 128, W = 128, HW = H * W;
        XPOSE(S1, O_XT0A, x0, 128, 128L * HW, flow0, 2, 2L * HW, H, W, 80);
        GTAP64(S1, 6, O_XT0A, off_b0, nullptr, 1440, 160, 64, 64, H, W,
               O_XT0B, 32, 0);
        GTAP(S1, 7, O_XT0B, co_b0, om0, 576, 64, 216, 216, H, W, 2);
        DCN(S1, O_SAMP0, x0 + 64L * HW, 128L * HW, om0, 64, H, W);
        GOLD64(S1, 8, O_SAMP0, dcn_b0, nullptr, 576, 64, 128, HW,
               O_XTF0, 64, 0);
        cudaEventRecord(g_s.eL0, S1);
    }

    // ---- s2: level 1 off/co/dcn chain (64x64) ----
    {
        const int H = 64, W = 64, HW = H * W;
        XPOSE(S2, O_XT1A, x1, 256, 256L * HW, flow1, 2, 2L * HW, H, W, 144);
        GTAP(S2, 3, O_XT1A, off_b1, nullptr, 2592, 288, 128, 128, H, W, 1,
             O_XT1B, 64, 0);
        GTAP(S2, 4, O_XT1B, co_b1, om1, 1152, 128, 216, 216, H, W, 2);
        DCN(S2, O_SAMP1, x1 + 128L * HW, 256L * HW, om1, 128, H, W);
        GOLD(S2, 5, O_SAMP1, dcn_b1, nullptr, 1152, 128, 256, HW, 1,
             O_XTF1, 128, 0);
        cudaEventRecord(g_s.eL1, S2);
    }

    // ---- origin: level 2 chain (32x32) + fusion cascade ----
    {
        const int H = 32, W = 32, HW = H * W;
        XPOSE(S0, O_XT2A, x2, 512, 512L * HW, flow2, 2, 2L * HW, H, W, 272);
        GTAP(S0, 0, O_XT2A, off_b2, nullptr, 4896, 544, 256, 256, H, W, 2,
             O_XT2B, 128, 0);
        GTAP(S0, 1, O_XT2B, co_b2, om2, 2304, 256, 216, 216, H, W, 2);
        DCN(S0, O_SAMP2, x2 + 256L * HW, 512L * HW, om2, 256, H, W);
        GOLD(S0, 2, O_SAMP2, dcn_b2, out2, 2304, 256, 256, HW, 2);
        UP2XT(S0, O_XTU1, out2, 256, H, W);
    }
    {   // level 1 fusion (64x64)
        const int H = 64, W = 64, HW = H * W;
        GTAP(S0, 9, O_XTU1, ch_b1, nullptr, 2304, 256, 128, 256, H, W, 1,
             O_XTF1, 128, 64);
        cudaStreamWaitEvent(S0, g_s.eL1, 0);
        GTAP(S0, 10, O_XTF1, ft_b1, out1, 2304, 256, 128, 128, H, W, 1);
        UP2XT(S0, O_XTU0, out1, 128, H, W);
    }
    {   // level 0 fusion (128x128)
        const int H = 128, W = 128, HW = H * W;
        GTAP64(S0, 11, O_XTU0, ch_b0, nullptr, 1152, 128, 64, 128, H, W,
               O_XTF0, 64, 32);
        cudaStreamWaitEvent(S0, g_s.eL0, 0);
        GTAP64(S0, 12, O_XTF0, ft_b0, out0, 1152, 128, 64, 64, H, W);
    }
}